// round 12
// baseline (speedup 1.0000x reference)
#include <cuda_runtime.h>
#include <cuda_bf16.h>
#include <cstdint>

// ---------------------------------------------------------------------------
// EncoderBiLSTMMaxPool, fused pipeline:
//   embed_split -> a2[16384 x 1024] bf16 [hi|lo]
//   w_split     -> w2[2][2048 x 1536] bf16 [hi|hi|lo]
//   gemm(full)  -> gx0 (layer-0 gates, all samples)
//   34 fused window kernels, grid 144 = 18 clusters of 8:
//     clusters 0-7 :  layer-0 recurrence, slot w     (h -> a2 split bf16)
//     clusters 8-15:  layer-1 recurrence, slot w-2   (h -> y1 in d_out)
//     clusters 16-17: GEMM role, 16 CTAs x 4 tiles -> gx1 for slot w-1
//   maxpool over batch axis.
// GEMM numerics: 3-term hi/lo split => fp32-accurate to ~1e-5.
// ---------------------------------------------------------------------------

#define Bn   128
#define Sn   128
#define Hn   512
#define NROW 16384
#define GXN  2048
#define KA   1024            // a2 row length (hi | lo)
#define KW   1536            // w2 row length (hi | hi | lo)

typedef unsigned long long ull;

__device__ __align__(16) float          g_x0[NROW * GXN];
__device__ __align__(16) float          g_x1[NROW * GXN];
__device__ __align__(16) __nv_bfloat16  g_a2[(long)NROW * KA];
__device__ __align__(16) __nv_bfloat16  g_w2[2L * GXN * KW];
__device__ float g_hs[2 * 8 * 256];
__device__ float g_cs[2 * 8 * 256];

// ---------------------------------------------------------------------------
// helpers
// ---------------------------------------------------------------------------
__device__ __forceinline__ unsigned smem_u32(const void* p) {
    return (unsigned)__cvta_generic_to_shared(p);
}
__device__ __forceinline__ unsigned mapa_cluster(unsigned addr, unsigned rank) {
    unsigned r;
    asm volatile("mapa.shared::cluster.u32 %0, %1, %2;" : "=r"(r) : "r"(addr), "r"(rank));
    return r;
}
__device__ __forceinline__ void cluster_sync_() {
    asm volatile("barrier.cluster.arrive.aligned;" ::: "memory");
    asm volatile("barrier.cluster.wait.aligned;" ::: "memory");
}
__device__ __forceinline__ void mbar_init(unsigned bar, unsigned cnt) {
    asm volatile("mbarrier.init.shared.b64 [%0], %1;" :: "r"(bar), "r"(cnt) : "memory");
}
__device__ __forceinline__ void mbar_arm(unsigned bar, unsigned tx) {
    asm volatile("mbarrier.arrive.expect_tx.shared::cta.b64 _, [%0], %1;"
                 :: "r"(bar), "r"(tx) : "memory");
}
__device__ __forceinline__ void mbar_wait(unsigned bar, unsigned parity) {
    asm volatile(
        "{\n\t.reg .pred P;\n"
        "LW%=:\n\t"
        "mbarrier.try_wait.parity.acquire.cta.shared::cta.b64 P, [%0], %1, 0x989680;\n\t"
        "@!P bra LW%=;\n\t}"
        :: "r"(bar), "r"(parity) : "memory");
}
__device__ __forceinline__ void st_async_f32(unsigned dst, float v, unsigned bar) {
    asm volatile("st.async.shared::cluster.mbarrier::complete_tx::bytes.b32 [%0], %1, [%2];"
                 :: "r"(dst), "r"(__float_as_uint(v)), "r"(bar) : "memory");
}
__device__ __forceinline__ float tanh_fast(float x) {
    float r;
    asm("tanh.approx.f32 %0, %1;" : "=f"(r) : "f"(x));
    return r;
}
__device__ __forceinline__ float sigmoid_fast(float x) {
    return fmaf(0.5f, tanh_fast(0.5f * x), 0.5f);
}
__device__ __forceinline__ void fma2(ull& acc, ull a, ull b) {
    asm("fma.rn.f32x2 %0, %1, %2, %0;" : "+l"(acc) : "l"(a), "l"(b));
}
__device__ __forceinline__ float sum2(ull a) {
    unsigned lo, hi;
    asm("mov.b64 {%0,%1}, %2;" : "=r"(lo), "=r"(hi) : "l"(a));
    return __uint_as_float(lo) + __uint_as_float(hi);
}

// --- mma.sync / ldmatrix / cp.async ---
__device__ __forceinline__ void cp16(unsigned dst, const void* src) {
    asm volatile("cp.async.cg.shared.global [%0], [%1], 16;" :: "r"(dst), "l"(src));
}
__device__ __forceinline__ void cp_commit() {
    asm volatile("cp.async.commit_group;" ::: "memory");
}
__device__ __forceinline__ void cp_wait3() {
    asm volatile("cp.async.wait_group 3;" ::: "memory");
}
__device__ __forceinline__ void ldsm4(unsigned* r, unsigned addr) {
    asm volatile("ldmatrix.sync.aligned.m8n8.x4.shared.b16 {%0,%1,%2,%3}, [%4];"
                 : "=r"(r[0]), "=r"(r[1]), "=r"(r[2]), "=r"(r[3]) : "r"(addr));
}
__device__ __forceinline__ void mma16816(float* c, const unsigned* a,
                                         unsigned b0, unsigned b1) {
    asm volatile(
        "mma.sync.aligned.m16n8k16.row.col.f32.bf16.bf16.f32 "
        "{%0,%1,%2,%3}, {%4,%5,%6,%7}, {%8,%9}, {%0,%1,%2,%3};"
        : "+f"(c[0]), "+f"(c[1]), "+f"(c[2]), "+f"(c[3])
        : "r"(a[0]), "r"(a[1]), "r"(a[2]), "r"(a[3]), "r"(b0), "r"(b1));
}

__device__ __forceinline__ uint2 pack4bf16(float a, float b, float c, float d) {
    __nv_bfloat162 p0 = __floats2bfloat162_rn(a, b);
    __nv_bfloat162 p1 = __floats2bfloat162_rn(c, d);
    uint2 r;
    r.x = *(unsigned*)&p0;
    r.y = *(unsigned*)&p1;
    return r;
}
__device__ __forceinline__ void split4(const float* v, float* hi, float* lo) {
#pragma unroll
    for (int j = 0; j < 4; j++) {
        __nv_bfloat16 h = __float2bfloat16_rn(v[j]);
        hi[j] = __bfloat162float(h);
        lo[j] = v[j] - hi[j];
    }
}

// ---------------------------------------------------------------------------
// 1) embedding sum + split -> a2 rows [hi | lo]
// ---------------------------------------------------------------------------
__global__ void embed_split_kernel(const int* __restrict__ rt, const int* __restrict__ re,
                                   const int* __restrict__ rm,
                                   const float* __restrict__ Ert, const float* __restrict__ Ere,
                                   const float* __restrict__ Erm)
{
    int row = blockIdx.x;
    int t   = threadIdx.x;
    long irt = rt[row], ire = re[row], irm = rm[row];
    float4 va = ((const float4*)(Ert + irt * (long)Hn))[t];
    float4 vb = ((const float4*)(Ere + ire * (long)Hn))[t];
    float4 vc = ((const float4*)(Erm + irm * (long)Hn))[t];
    float v[4] = { va.x + vb.x + vc.x, va.y + vb.y + vc.y,
                   va.z + vb.z + vc.z, va.w + vb.w + vc.w };
    float hi[4], lo[4];
    split4(v, hi, lo);
    __nv_bfloat16* ro = g_a2 + (long)row * KA + 4 * t;
    *(uint2*)(ro)       = pack4bf16(hi[0], hi[1], hi[2], hi[3]);
    *(uint2*)(ro + 512) = pack4bf16(lo[0], lo[1], lo[2], lo[3]);
}

// split Wih -> w2 rows [hi | hi | lo]
__global__ void w_split_kernel(const float* __restrict__ Wih)
{
    int n = blockIdx.x;
    int l = blockIdx.y;
    int t = threadIdx.x;
    float4 vv = *(const float4*)(Wih + ((long)l * 2048 + n) * 512 + 4 * t);
    float v[4] = { vv.x, vv.y, vv.z, vv.w };
    float hi[4], lo[4];
    split4(v, hi, lo);
    __nv_bfloat16* ro = g_w2 + ((long)l * 2048 + n) * KW + 4 * t;
    uint2 ph = pack4bf16(hi[0], hi[1], hi[2], hi[3]);
    *(uint2*)(ro)        = ph;
    *(uint2*)(ro + 512)  = ph;
    *(uint2*)(ro + 1024) = pack4bf16(lo[0], lo[1], lo[2], lo[3]);
}

// ---------------------------------------------------------------------------
// 2) one 128x128xK=1536 mma.sync tile (shared by standalone GEMM + window role)
//    5-stage cp.async pipeline, A k-map (k>=1024 re-reads hi block).
// ---------------------------------------------------------------------------
#define ROWB       80
#define A_BYTES    (128 * ROWB)
#define STAGE_B    (2 * A_BYTES)          // 20480
#define NSTAGE     5
#define GEMM_SMEM  (NSTAGE * STAGE_B)     // 102400
#define NKT        (KW / 32)              // 48

__device__ void gemm_tile(const __nv_bfloat16* __restrict__ A2,
                          const __nv_bfloat16* __restrict__ W2,
                          const float* __restrict__ bih, const float* __restrict__ bhh,
                          float* __restrict__ C, int bm, int bn,
                          char* dyn, float* bias_s)
{
    const int tid  = threadIdx.x;
    const int wid  = tid >> 5;
    const int lane = tid & 31;
    const int wm   = wid & 3;
    const int wn   = wid >> 2;

    __syncthreads();                        // smem reuse guard (tiles / roles)
    if (tid < 128) bias_s[tid] = bih[bn + tid] + bhh[bn + tid];

    const unsigned sbase = smem_u32(dyn);
    const int g  = lane >> 3;
    const int rr = lane & 7;
    const unsigned a_lane = (unsigned)((wm * 32 + (g & 1) * 8 + rr) * ROWB + (g >> 1) * 16);
    const unsigned b_lane = (unsigned)((wn * 64 + (g >> 1) * 8 + rr) * ROWB + (g & 1) * 16);

    float acc[2][8][4];
#pragma unroll
    for (int i = 0; i < 2; i++)
#pragma unroll
        for (int j = 0; j < 8; j++)
#pragma unroll
            for (int q = 0; q < 4; q++) acc[i][j][q] = 0.f;

    auto issue_loads = [&](int kt) {
        unsigned stage = sbase + (unsigned)(kt % NSTAGE) * STAGE_B;
        long k0 = (long)kt * 32;
        long ak = (k0 < 1024) ? k0 : (k0 - 1024);
#pragma unroll
        for (int i = 0; i < 4; i++) {
            int c = tid + i * 256;
            if (c < 512) {
                int row = c >> 2, ch = c & 3;
                cp16(stage + row * ROWB + ch * 16,
                     A2 + (long)(bm + row) * KA + ak + ch * 8);
            } else {
                int c2 = c - 512;
                int row = c2 >> 2, ch = c2 & 3;
                cp16(stage + A_BYTES + row * ROWB + ch * 16,
                     W2 + (long)(bn + row) * KW + k0 + ch * 8);
            }
        }
    };

    issue_loads(0); cp_commit();
    issue_loads(1); cp_commit();
    issue_loads(2); cp_commit();
    issue_loads(3); cp_commit();

    for (int kt = 0; kt < NKT; kt++) {
        cp_wait3();
        __syncthreads();
        unsigned stage  = sbase + (unsigned)(kt % NSTAGE) * STAGE_B;
        unsigned stageB = stage + A_BYTES;
#pragma unroll
        for (int kk = 0; kk < 2; kk++) {
            unsigned afrag[2][4];
#pragma unroll
            for (int mi = 0; mi < 2; mi++)
                ldsm4(afrag[mi], stage + a_lane + mi * 16 * ROWB + kk * 32);
            unsigned bfrag[4][4];
#pragma unroll
            for (int p = 0; p < 4; p++)
                ldsm4(bfrag[p], stageB + b_lane + p * 16 * ROWB + kk * 32);
#pragma unroll
            for (int mi = 0; mi < 2; mi++)
#pragma unroll
                for (int p = 0; p < 4; p++) {
                    mma16816(acc[mi][2 * p],     afrag[mi], bfrag[p][0], bfrag[p][1]);
                    mma16816(acc[mi][2 * p + 1], afrag[mi], bfrag[p][2], bfrag[p][3]);
                }
        }
        __syncthreads();
        if (kt + 4 < NKT) issue_loads(kt + 4);
        cp_commit();
    }

    const int trow = lane >> 2;
    const int tcol = (lane & 3) * 2;
#pragma unroll
    for (int mi = 0; mi < 2; mi++) {
        int m0 = bm + wm * 32 + mi * 16 + trow;
#pragma unroll
        for (int nj = 0; nj < 8; nj++) {
            int cl = wn * 64 + nj * 8 + tcol;
            int n0 = bn + cl;
            float b0 = bias_s[cl], b1 = bias_s[cl + 1];
            *(float2*)(C + (long)m0 * GXN + n0) =
                make_float2(acc[mi][nj][0] + b0, acc[mi][nj][1] + b1);
            *(float2*)(C + (long)(m0 + 8) * GXN + n0) =
                make_float2(acc[mi][nj][2] + b0, acc[mi][nj][3] + b1);
        }
    }
}

// standalone GEMM (used for the full layer-0 gate GEMM)
__global__ __launch_bounds__(256, 1) void gemm_mma_kernel(
    const __nv_bfloat16* __restrict__ A2, const __nv_bfloat16* __restrict__ W2,
    const float* __restrict__ bih, const float* __restrict__ bhh,
    float* __restrict__ C)
{
    extern __shared__ __align__(16) char dyn[];
    __shared__ float bias_s[128];
    gemm_tile(A2, W2, bih, bhh, C, blockIdx.y * 128, blockIdx.x * 128, dyn, bias_s);
}

// ---------------------------------------------------------------------------
// 3) fused window kernel. Grid 144 = 18 clusters of 8:
//    clusters 0-7:  layer-0 lstm, slot w
//    clusters 8-15: layer-1 lstm, slot w-2
//    clusters 16-17: GEMM role -> gx1 tiles for slot w-1 (16 CTAs x 4 tiles)
// ---------------------------------------------------------------------------
__global__ void __cluster_dims__(8, 1, 1) __launch_bounds__(256, 1)
lstm_window_kernel(const float* __restrict__ Whh,
                   const float* __restrict__ gx0, float* __restrict__ gx1,
                   float* __restrict__ y1, __nv_bfloat16* __restrict__ a2,
                   const __nv_bfloat16* __restrict__ w2l1,
                   const float* __restrict__ bih1, const float* __restrict__ bhh1,
                   const float* __restrict__ h0, const float* __restrict__ c0,
                   float* __restrict__ h_state, float* __restrict__ c_state,
                   int w)
{
    extern __shared__ __align__(16) char dyn[];
    __shared__ __align__(16) float h_buf[2][256];
    __shared__ float partial[256];
    __shared__ float bias_s[128];
    __shared__ __align__(8) ull mbar[2];

    unsigned rank;
    asm("mov.u32 %0, %%cluster_ctarank;" : "=r"(rank));
    const int cluster_id = blockIdx.x >> 3;

    // ---- GEMM role: gx1 tiles for slot w-1 ----
    if (cluster_id >= 16) {
        int slot = w - 1;
        if (slot < 0 || slot > 31) return;
        int cta = (cluster_id - 16) * 8 + (int)rank;    // 0..15
#pragma unroll 1
        for (int t = 0; t < 4; t++) {
            int tile = cta * 4 + t;                      // 0..63
            int sb = tile >> 4;                          // group 0..3
            int nt = tile & 15;                          // n-tile 0..15
            gemm_tile(a2, w2l1, bih1, bhh1, gx1,
                      (sb * 32 + slot) * 128, nt * 128, dyn, bias_s);
        }
        return;
    }

    // ---- LSTM roles ----
    const int layer = cluster_id >> 3;        // 0 or 1
    const int sub   = cluster_id & 7;
    const int group = sub & 3;
    const int dir   = sub >> 2;
    const int bl = (layer == 0) ? w : (w - 2);
    if (bl < 0 || bl >= 32) return;

    const int tid = threadIdx.x;
    const int row_local = tid & 127;
    const int half = tid >> 7;
    const int gate = row_local >> 5;
    const int ul   = row_local & 31;
    const int unit = (int)rank * 32 + ul;
    const int grow = gate * 256 + unit;

    ulonglong2 wreg[32];
    const ulonglong2* wsrc = (const ulonglong2*)(Whh
        + ((long)(layer * 2 + dir) * 1024 + grow) * 256 + half * 128);
#pragma unroll
    for (int j = 0; j < 32; j++) wreg[j] = wsrc[j];

    const int chain = layer * 8 + sub;
    const int sidx  = (layer * 2 + dir) * 256;
    float creg = 0.f;
    if (bl == 0) {
        h_buf[0][tid] = (group == 0) ? h0[sidx + tid] : 0.f;
        if (tid < 32) creg = (group == 0) ? c0[sidx + (int)rank * 32 + tid] : 0.f;
    } else {
        h_buf[0][tid] = h_state[chain * 256 + tid];
        if (tid < 32) creg = c_state[chain * 256 + (int)rank * 32 + tid];
    }

    unsigned mb0 = smem_u32(&mbar[0]);
    unsigned mb1 = smem_u32(&mbar[1]);
    if (tid == 0) {
        mbar_init(mb0, 1);
        mbar_init(mb1, 1);
        mbar_arm(mb1, 1024);
        mbar_arm(mb0, 1024);
    }
    __syncthreads();
    cluster_sync_();

    const float* gx = layer ? gx1 : gx0;
    const int xcol = dir * 1024 + grow;
    const int ycol = dir * 256 + unit;
    const long mrow0 = ((long)group * 32 + bl) * 128;
    unsigned ph0 = 0, ph1 = 0;

    auto midx = [&](int q) -> long {
        int t = dir ? (127 - q) : q;
        return mrow0 + t;
    };

    float xcur = (tid < 128) ? __ldg(gx + midx(0) * GXN + xcol) : 0.f;

    for (int q = 0; q < 128; q++) {
        const int p = q & 1;

        float xnext = 0.f;
        if (tid < 128 && q + 1 < 128)
            xnext = __ldg(gx + midx(q + 1) * GXN + xcol);

        if (q > 0) {
            if (p) { mbar_wait(mb1, ph1); ph1 ^= 1; }
            else   { mbar_wait(mb0, ph0); ph0 ^= 1; }
            if (tid == 1) mbar_arm(p ? mb1 : mb0, 1024);
        }

        const ulonglong2* hb = ((const ulonglong2*)h_buf[p]) + half * 32;
        ull acc0 = 0, acc1 = 0;
#pragma unroll
        for (int j = 0; j < 32; j++) {
            ulonglong2 hv = hb[j];
            fma2(acc0, hv.x, wreg[j].x);
            fma2(acc1, hv.y, wreg[j].y);
        }
        float s = sum2(acc0) + sum2(acc1);
        partial[tid] = (tid < 128) ? (s + xcur) : s;
        __syncthreads();

        if (tid < 32) {
            float iv = partial[tid]      + partial[tid + 128];
            float fv = partial[tid + 32] + partial[tid + 160];
            float gv = partial[tid + 64] + partial[tid + 192];
            float ov = partial[tid + 96] + partial[tid + 224];
            float ig = sigmoid_fast(iv);
            float fg = sigmoid_fast(fv);
            float og = sigmoid_fast(ov);
            float gg = tanh_fast(gv);
            creg = fmaf(fg, creg, ig * gg);
            float h = og * tanh_fast(creg);

            const long m = midx(q);
            if (layer == 0) {
                __nv_bfloat16 hb16 = __float2bfloat16_rn(h);
                float hf = __bfloat162float(hb16);
                __nv_bfloat16 lb16 = __float2bfloat16_rn(h - hf);
                a2[m * KA + ycol]       = hb16;
                a2[m * KA + 512 + ycol] = lb16;
            } else {
                y1[m * Hn + ycol] = h;
            }
            if (q == 127) {
                h_state[chain * 256 + unit] = h;
                c_state[chain * 256 + unit] = creg;
            }

            const int pn = p ^ 1;
            unsigned ldst = smem_u32(&h_buf[pn][unit]);
            unsigned lbar = pn ? mb1 : mb0;
#pragma unroll
            for (unsigned r = 0; r < 8; r++)
                st_async_f32(mapa_cluster(ldst, r), h, mapa_cluster(lbar, r));
        }
        xcur = xnext;
    }

    mbar_wait(mb0, ph0);
    cluster_sync_();
}

// ---------------------------------------------------------------------------
// 5) max over batch axis
// ---------------------------------------------------------------------------
__global__ void maxpool_kernel(const float* __restrict__ y1, float* __restrict__ out2)
{
    int idx = blockIdx.x * 256 + threadIdx.x;
    int s = idx >> 9, h = idx & 511;
    float mx = -3.402823466e38f;
    for (int b = 0; b < 128; b++) {
        float v = y1[((long)b * 128 + s) * Hn + h];
        mx = fmaxf(mx, v);
    }
    out2[idx] = mx;
}

// ---------------------------------------------------------------------------
extern "C" void kernel_launch(void* const* d_in, const int* in_sizes, int n_in,
                              void* d_out, int out_size)
{
    const int*   rt  = (const int*)d_in[0];
    const int*   re  = (const int*)d_in[1];
    const int*   rm  = (const int*)d_in[2];
    const float* h0  = (const float*)d_in[3];
    const float* c0  = (const float*)d_in[4];
    const float* Ert = (const float*)d_in[5];
    const float* Ere = (const float*)d_in[6];
    const float* Erm = (const float*)d_in[7];
    const float* Wih = (const float*)d_in[8];
    const float* Whh = (const float*)d_in[9];
    const float* bih = (const float*)d_in[10];
    const float* bhh = (const float*)d_in[11];

    float* out  = (float*)d_out;
    float* y1   = out;
    float* out2 = out + (long)Bn * Sn * Hn;

    void *p_x0, *p_x1, *p_a2, *p_w2, *p_hs, *p_cs;
    cudaGetSymbolAddress(&p_x0, g_x0);
    cudaGetSymbolAddress(&p_x1, g_x1);
    cudaGetSymbolAddress(&p_a2, g_a2);
    cudaGetSymbolAddress(&p_w2, g_w2);
    cudaGetSymbolAddress(&p_hs, g_hs);
    cudaGetSymbolAddress(&p_cs, g_cs);
    float* gx0 = (float*)p_x0;
    float* gx1 = (float*)p_x1;
    __nv_bfloat16* a2 = (__nv_bfloat16*)p_a2;
    __nv_bfloat16* w2 = (__nv_bfloat16*)p_w2;
    float* hs = (float*)p_hs;
    float* cs = (float*)p_cs;

    cudaFuncSetAttribute(gemm_mma_kernel,
                         cudaFuncAttributeMaxDynamicSharedMemorySize, GEMM_SMEM);
    cudaFuncSetAttribute(lstm_window_kernel,
                         cudaFuncAttributeMaxDynamicSharedMemorySize, GEMM_SMEM);

    // prep
    embed_split_kernel<<<NROW, 128>>>(rt, re, rm, Ert, Ere, Erm);
    w_split_kernel<<<dim3(2048, 2), 128>>>(Wih);

    // layer-0 input GEMM over all 128 samples
    gemm_mma_kernel<<<dim3(16, 128), 256, GEMM_SMEM>>>(a2, w2, bih, bhh, gx0);

    // fused pipelined windows:
    //   w:      layer-0 slot w, GEMM slot w-1, layer-1 slot w-2
    const __nv_bfloat16* w2l1 = w2 + (long)2048 * KW;
    for (int w = 0; w <= 33; w++) {
        lstm_window_kernel<<<144, 256, GEMM_SMEM>>>(
            Whh, gx0, gx1, y1, a2, w2l1, bih + 2048, bhh + 2048,
            h0, c0, hs, cs, w);
    }

    maxpool_kernel<<<256, 256>>>(y1, out2);
}

// round 13
// speedup vs baseline: 1.4629x; 1.4629x over previous
#include <cuda_runtime.h>
#include <cuda_bf16.h>
#include <cstdint>

// ---------------------------------------------------------------------------
// EncoderBiLSTMMaxPool, fully pipelined via persistent kernels + flags:
//   zero_flags; embed_split -> a2 [hi|lo]; w_split -> w2 [hi|hi|lo]
//   gemm0 (full 2048-tile mma.sync GEMM) -> gx0
//   FORK (non-blocking stream + events):
//     branch A: lstm_fused, 128 CTAs = 16 clusters of 8
//        clusters 0-7:  layer-0, 4096 steps; h -> a2 (split bf16); per-sample
//                       flag f0[s*4+g] += 1  (16 CTAs per (g,s))
//        clusters 8-15: layer-1, 4096 steps; per-sample wait f1[s*4+g]==16;
//                       h -> y1 (d_out)
//     branch B: gemm_pipe, 24 persistent CTAs on the 24 SMs lstm leaves idle;
//        2048 tiles in lstm0-completion order, gated on f0, posting f1.
//   JOIN; maxpool.
// GEMM numerics: 3-term hi/lo split => fp32-accurate ~5e-6 (proven R8-R12).
// ---------------------------------------------------------------------------

#define Bn   128
#define Sn   128
#define Hn   512
#define NROW 16384
#define GXN  2048
#define KA   1024
#define KW   1536
#define NG   24              // persistent gemm CTAs

typedef unsigned long long ull;

__device__ __align__(16) float          g_x0[NROW * GXN];
__device__ __align__(16) float          g_x1[NROW * GXN];
__device__ __align__(16) __nv_bfloat16  g_a2[(long)NROW * KA];
__device__ __align__(16) __nv_bfloat16  g_w2[2L * GXN * KW];
__device__ unsigned g_f0[128];    // (s*4+g): a2 sample-block ready (target 16)
__device__ unsigned g_f1[128];    // (s*4+g): gx1 m-tile ready     (target 16)

// ---------------------------------------------------------------------------
// helpers
// ---------------------------------------------------------------------------
__device__ __forceinline__ unsigned smem_u32(const void* p) {
    return (unsigned)__cvta_generic_to_shared(p);
}
__device__ __forceinline__ unsigned mapa_cluster(unsigned addr, unsigned rank) {
    unsigned r;
    asm volatile("mapa.shared::cluster.u32 %0, %1, %2;" : "=r"(r) : "r"(addr), "r"(rank));
    return r;
}
__device__ __forceinline__ void cluster_sync_() {
    asm volatile("barrier.cluster.arrive.aligned;" ::: "memory");
    asm volatile("barrier.cluster.wait.aligned;" ::: "memory");
}
__device__ __forceinline__ void mbar_init(unsigned bar, unsigned cnt) {
    asm volatile("mbarrier.init.shared.b64 [%0], %1;" :: "r"(bar), "r"(cnt) : "memory");
}
__device__ __forceinline__ void mbar_arm(unsigned bar, unsigned tx) {
    asm volatile("mbarrier.arrive.expect_tx.shared::cta.b64 _, [%0], %1;"
                 :: "r"(bar), "r"(tx) : "memory");
}
__device__ __forceinline__ void mbar_wait(unsigned bar, unsigned parity) {
    asm volatile(
        "{\n\t.reg .pred P;\n"
        "LW%=:\n\t"
        "mbarrier.try_wait.parity.acquire.cta.shared::cta.b64 P, [%0], %1, 0x989680;\n\t"
        "@!P bra LW%=;\n\t}"
        :: "r"(bar), "r"(parity) : "memory");
}
__device__ __forceinline__ void st_async_f32(unsigned dst, float v, unsigned bar) {
    asm volatile("st.async.shared::cluster.mbarrier::complete_tx::bytes.b32 [%0], %1, [%2];"
                 :: "r"(dst), "r"(__float_as_uint(v)), "r"(bar) : "memory");
}
__device__ __forceinline__ float tanh_fast(float x) {
    float r;
    asm("tanh.approx.f32 %0, %1;" : "=f"(r) : "f"(x));
    return r;
}
__device__ __forceinline__ float sigmoid_fast(float x) {
    return fmaf(0.5f, tanh_fast(0.5f * x), 0.5f);
}
__device__ __forceinline__ void fma2(ull& acc, ull a, ull b) {
    asm("fma.rn.f32x2 %0, %1, %2, %0;" : "+l"(acc) : "l"(a), "l"(b));
}
__device__ __forceinline__ float sum2(ull a) {
    unsigned lo, hi;
    asm("mov.b64 {%0,%1}, %2;" : "=r"(lo), "=r"(hi) : "l"(a));
    return __uint_as_float(lo) + __uint_as_float(hi);
}
__device__ __forceinline__ unsigned ld_acq(const unsigned* p) {
    unsigned v;
    asm volatile("ld.acquire.gpu.global.u32 %0, [%1];" : "=r"(v) : "l"(p) : "memory");
    return v;
}

// --- mma.sync / ldmatrix / cp.async ---
__device__ __forceinline__ void cp16(unsigned dst, const void* src) {
    asm volatile("cp.async.cg.shared.global [%0], [%1], 16;" :: "r"(dst), "l"(src));
}
__device__ __forceinline__ void cp_commit() {
    asm volatile("cp.async.commit_group;" ::: "memory");
}
__device__ __forceinline__ void cp_wait3() {
    asm volatile("cp.async.wait_group 3;" ::: "memory");
}
__device__ __forceinline__ void ldsm4(unsigned* r, unsigned addr) {
    asm volatile("ldmatrix.sync.aligned.m8n8.x4.shared.b16 {%0,%1,%2,%3}, [%4];"
                 : "=r"(r[0]), "=r"(r[1]), "=r"(r[2]), "=r"(r[3]) : "r"(addr));
}
__device__ __forceinline__ void mma16816(float* c, const unsigned* a,
                                         unsigned b0, unsigned b1) {
    asm volatile(
        "mma.sync.aligned.m16n8k16.row.col.f32.bf16.bf16.f32 "
        "{%0,%1,%2,%3}, {%4,%5,%6,%7}, {%8,%9}, {%0,%1,%2,%3};"
        : "+f"(c[0]), "+f"(c[1]), "+f"(c[2]), "+f"(c[3])
        : "r"(a[0]), "r"(a[1]), "r"(a[2]), "r"(a[3]), "r"(b0), "r"(b1));
}

__device__ __forceinline__ uint2 pack4bf16(float a, float b, float c, float d) {
    __nv_bfloat162 p0 = __floats2bfloat162_rn(a, b);
    __nv_bfloat162 p1 = __floats2bfloat162_rn(c, d);
    uint2 r;
    r.x = *(unsigned*)&p0;
    r.y = *(unsigned*)&p1;
    return r;
}
__device__ __forceinline__ void split4(const float* v, float* hi, float* lo) {
#pragma unroll
    for (int j = 0; j < 4; j++) {
        __nv_bfloat16 h = __float2bfloat16_rn(v[j]);
        hi[j] = __bfloat162float(h);
        lo[j] = v[j] - hi[j];
    }
}

// ---------------------------------------------------------------------------
// 0) flag reset (runs at the head of every graph replay)
// ---------------------------------------------------------------------------
__global__ void zero_flags_kernel()
{
    int t = threadIdx.x;
    if (t < 128) { g_f0[t] = 0; g_f1[t] = 0; }
}

// ---------------------------------------------------------------------------
// 1) embedding sum + split -> a2 rows [hi | lo]
// ---------------------------------------------------------------------------
__global__ void embed_split_kernel(const int* __restrict__ rt, const int* __restrict__ re,
                                   const int* __restrict__ rm,
                                   const float* __restrict__ Ert, const float* __restrict__ Ere,
                                   const float* __restrict__ Erm)
{
    int row = blockIdx.x;
    int t   = threadIdx.x;
    long irt = rt[row], ire = re[row], irm = rm[row];
    float4 va = ((const float4*)(Ert + irt * (long)Hn))[t];
    float4 vb = ((const float4*)(Ere + ire * (long)Hn))[t];
    float4 vc = ((const float4*)(Erm + irm * (long)Hn))[t];
    float v[4] = { va.x + vb.x + vc.x, va.y + vb.y + vc.y,
                   va.z + vb.z + vc.z, va.w + vb.w + vc.w };
    float hi[4], lo[4];
    split4(v, hi, lo);
    __nv_bfloat16* ro = g_a2 + (long)row * KA + 4 * t;
    *(uint2*)(ro)       = pack4bf16(hi[0], hi[1], hi[2], hi[3]);
    *(uint2*)(ro + 512) = pack4bf16(lo[0], lo[1], lo[2], lo[3]);
}

// split Wih -> w2 rows [hi | hi | lo]
__global__ void w_split_kernel(const float* __restrict__ Wih)
{
    int n = blockIdx.x;
    int l = blockIdx.y;
    int t = threadIdx.x;
    float4 vv = *(const float4*)(Wih + ((long)l * 2048 + n) * 512 + 4 * t);
    float v[4] = { vv.x, vv.y, vv.z, vv.w };
    float hi[4], lo[4];
    split4(v, hi, lo);
    __nv_bfloat16* ro = g_w2 + ((long)l * 2048 + n) * KW + 4 * t;
    uint2 ph = pack4bf16(hi[0], hi[1], hi[2], hi[3]);
    *(uint2*)(ro)        = ph;
    *(uint2*)(ro + 512)  = ph;
    *(uint2*)(ro + 1024) = pack4bf16(lo[0], lo[1], lo[2], lo[3]);
}

// ---------------------------------------------------------------------------
// 2) one 128x128xK=1536 mma.sync tile; 5-stage cp.async pipeline;
//    A k-map (k>=1024 re-reads hi block).
// ---------------------------------------------------------------------------
#define ROWB       80
#define A_BYTES    (128 * ROWB)
#define STAGE_B    (2 * A_BYTES)          // 20480
#define NSTAGE     5
#define GEMM_SMEM  (NSTAGE * STAGE_B)     // 102400
#define NKT        (KW / 32)              // 48

__device__ void gemm_tile(const __nv_bfloat16* __restrict__ A2,
                          const __nv_bfloat16* __restrict__ W2,
                          const float* __restrict__ bih, const float* __restrict__ bhh,
                          float* __restrict__ C, int bm, int bn,
                          char* dyn, float* bias_s)
{
    const int tid  = threadIdx.x;
    const int wid  = tid >> 5;
    const int lane = tid & 31;
    const int wm   = wid & 3;
    const int wn   = wid >> 2;

    __syncthreads();                       // smem reuse guard across tiles
    if (tid < 128) bias_s[tid] = bih[bn + tid] + bhh[bn + tid];

    const unsigned sbase = smem_u32(dyn);
    const int g  = lane >> 3;
    const int rr = lane & 7;
    const unsigned a_lane = (unsigned)((wm * 32 + (g & 1) * 8 + rr) * ROWB + (g >> 1) * 16);
    const unsigned b_lane = (unsigned)((wn * 64 + (g >> 1) * 8 + rr) * ROWB + (g & 1) * 16);

    float acc[2][8][4];
#pragma unroll
    for (int i = 0; i < 2; i++)
#pragma unroll
        for (int j = 0; j < 8; j++)
#pragma unroll
            for (int q = 0; q < 4; q++) acc[i][j][q] = 0.f;

    auto issue_loads = [&](int kt) {
        unsigned stage = sbase + (unsigned)(kt % NSTAGE) * STAGE_B;
        long k0 = (long)kt * 32;
        long ak = (k0 < 1024) ? k0 : (k0 - 1024);
#pragma unroll
        for (int i = 0; i < 4; i++) {
            int c = tid + i * 256;
            if (c < 512) {
                int row = c >> 2, ch = c & 3;
                cp16(stage + row * ROWB + ch * 16,
                     A2 + (long)(bm + row) * KA + ak + ch * 8);
            } else {
                int c2 = c - 512;
                int row = c2 >> 2, ch = c2 & 3;
                cp16(stage + A_BYTES + row * ROWB + ch * 16,
                     W2 + (long)(bn + row) * KW + k0 + ch * 8);
            }
        }
    };

    issue_loads(0); cp_commit();
    issue_loads(1); cp_commit();
    issue_loads(2); cp_commit();
    issue_loads(3); cp_commit();

    for (int kt = 0; kt < NKT; kt++) {
        cp_wait3();
        __syncthreads();
        unsigned stage  = sbase + (unsigned)(kt % NSTAGE) * STAGE_B;
        unsigned stageB = stage + A_BYTES;
#pragma unroll
        for (int kk = 0; kk < 2; kk++) {
            unsigned afrag[2][4];
#pragma unroll
            for (int mi = 0; mi < 2; mi++)
                ldsm4(afrag[mi], stage + a_lane + mi * 16 * ROWB + kk * 32);
            unsigned bfrag[4][4];
#pragma unroll
            for (int p = 0; p < 4; p++)
                ldsm4(bfrag[p], stageB + b_lane + p * 16 * ROWB + kk * 32);
#pragma unroll
            for (int mi = 0; mi < 2; mi++)
#pragma unroll
                for (int p = 0; p < 4; p++) {
                    mma16816(acc[mi][2 * p],     afrag[mi], bfrag[p][0], bfrag[p][1]);
                    mma16816(acc[mi][2 * p + 1], afrag[mi], bfrag[p][2], bfrag[p][3]);
                }
        }
        __syncthreads();
        if (kt + 4 < NKT) issue_loads(kt + 4);
        cp_commit();
    }

    const int trow = lane >> 2;
    const int tcol = (lane & 3) * 2;
#pragma unroll
    for (int mi = 0; mi < 2; mi++) {
        int m0 = bm + wm * 32 + mi * 16 + trow;
#pragma unroll
        for (int nj = 0; nj < 8; nj++) {
            int cl = wn * 64 + nj * 8 + tcol;
            int n0 = bn + cl;
            float b0 = bias_s[cl], b1 = bias_s[cl + 1];
            *(float2*)(C + (long)m0 * GXN + n0) =
                make_float2(acc[mi][nj][0] + b0, acc[mi][nj][1] + b1);
            *(float2*)(C + (long)(m0 + 8) * GXN + n0) =
                make_float2(acc[mi][nj][2] + b0, acc[mi][nj][3] + b1);
        }
    }
}

// standalone GEMM: gx0 for all samples (bm = by*128)
__global__ __launch_bounds__(256, 2) void gemm_mma_kernel(
    const __nv_bfloat16* __restrict__ A2, const __nv_bfloat16* __restrict__ W2,
    const float* __restrict__ bih, const float* __restrict__ bhh,
    float* __restrict__ C)
{
    extern __shared__ __align__(16) char dyn[];
    __shared__ float bias_s[128];
    gemm_tile(A2, W2, bih, bhh, C, blockIdx.y * 128, blockIdx.x * 128, dyn, bias_s);
}

// persistent gemm: 24 CTAs, 2048 tiles in lstm0-completion order, flag-gated
__global__ __launch_bounds__(256, 1) void gemm_pipe_kernel(
    const __nv_bfloat16* __restrict__ A2, const __nv_bfloat16* __restrict__ W2,
    const float* __restrict__ bih, const float* __restrict__ bhh,
    float* __restrict__ C)
{
    extern __shared__ __align__(16) char dyn[];
    __shared__ float bias_s[128];
    const int tid = threadIdx.x;
    const int c = blockIdx.x;

    for (int t = c; t < 2048; t += NG) {
        const int fi = t >> 4;            // completion-order index: s*4+g
        const int nt = t & 15;
        const int g = fi & 3;
        const int s = fi >> 2;
        const int mtile = g * 32 + s;

        if (tid == 0) {
            while (ld_acq(&g_f0[fi]) < 16u) __nanosleep(128);
        }
        __syncthreads();
        __threadfence();                  // acquire a2 data written by lstm0

        gemm_tile(A2, W2, bih, bhh, C, mtile * 128, nt * 128, dyn, bias_s);

        __threadfence();                  // publish gx1 tile
        __syncthreads();
        if (tid == 0) atomicAdd(&g_f1[fi], 1u);
    }
}

// ---------------------------------------------------------------------------
// 3) fused persistent LSTM: 16 clusters of 8. clusters 0-7 layer 0,
//    clusters 8-15 layer 1. Full 32 samples x 128 steps per cluster, state
//    resident. layer0 posts f0 per sample; layer1 gates on f1 per sample.
// ---------------------------------------------------------------------------
__global__ void __cluster_dims__(8, 1, 1) __launch_bounds__(256, 1)
lstm_fused_kernel(const float* __restrict__ Whh,
                  const float* __restrict__ gx0, const float* __restrict__ gx1,
                  float* __restrict__ y1, __nv_bfloat16* __restrict__ a2,
                  const float* __restrict__ h0, const float* __restrict__ c0)
{
    __shared__ __align__(16) float h_buf[2][256];
    __shared__ float partial[256];
    __shared__ __align__(8) ull mbar[2];

    const int cluster_id = blockIdx.x >> 3;   // 0..15
    const int layer = cluster_id >> 3;
    const int sub   = cluster_id & 7;
    const int group = sub & 3;
    const int dir   = sub >> 2;

    unsigned rank;
    asm("mov.u32 %0, %%cluster_ctarank;" : "=r"(rank));
    const int tid = threadIdx.x;
    const int row_local = tid & 127;
    const int half = tid >> 7;
    const int gate = row_local >> 5;
    const int ul   = row_local & 31;
    const int unit = (int)rank * 32 + ul;
    const int grow = gate * 256 + unit;

    ulonglong2 wreg[32];
    const ulonglong2* wsrc = (const ulonglong2*)(Whh
        + ((long)(layer * 2 + dir) * 1024 + grow) * 256 + half * 128);
#pragma unroll
    for (int j = 0; j < 32; j++) wreg[j] = wsrc[j];

    const int sidx = (layer * 2 + dir) * 256;
    h_buf[0][tid] = (group == 0) ? h0[sidx + tid] : 0.f;
    float creg = 0.f;
    if (tid < 32) creg = (group == 0) ? c0[sidx + (int)rank * 32 + tid] : 0.f;

    unsigned mb0 = smem_u32(&mbar[0]);
    unsigned mb1 = smem_u32(&mbar[1]);
    if (tid == 0) {
        mbar_init(mb0, 1);
        mbar_init(mb1, 1);
        mbar_arm(mb1, 1024);   // consumed at q=1
        mbar_arm(mb0, 1024);   // consumed at q=2
    }
    __syncthreads();
    cluster_sync_();

    const float* gx = layer ? gx1 : gx0;
    const int xcol = dir * 1024 + grow;
    const int ycol = dir * 256 + unit;
    unsigned ph0 = 0, ph1 = 0;

    for (int s = 0; s < 32; s++) {
        // layer-1: wait for gemm_pipe to finish this sample's gx1 m-tile
        if (layer == 1) {
            const int fi = s * 4 + group;
            if (tid == 0) {
                while (ld_acq(&g_f1[fi]) < 16u) __nanosleep(128);
            }
            __syncthreads();
            __threadfence();              // acquire gx1 data
        }

        const long mrow0 = ((long)group * 32 + s) * 128;
        auto midx = [&](int qi) -> long {
            int tt = dir ? (127 - qi) : qi;
            return mrow0 + tt;
        };

        float xcur = (tid < 128) ? __ldg(gx + midx(0) * GXN + xcol) : 0.f;

        for (int qi = 0; qi < 128; qi++) {
            const int q = s * 128 + qi;
            const int p = q & 1;

            float xnext = 0.f;
            if (tid < 128 && qi + 1 < 128)
                xnext = __ldg(gx + midx(qi + 1) * GXN + xcol);

            if (q > 0) {
                if (p) { mbar_wait(mb1, ph1); ph1 ^= 1; }
                else   { mbar_wait(mb0, ph0); ph0 ^= 1; }
                if (tid == 1) mbar_arm(p ? mb1 : mb0, 1024);
            }

            const ulonglong2* hb = ((const ulonglong2*)h_buf[p]) + half * 32;
            ull acc0 = 0, acc1 = 0;
#pragma unroll
            for (int j = 0; j < 32; j++) {
                ulonglong2 hv = hb[j];
                fma2(acc0, hv.x, wreg[j].x);
                fma2(acc1, hv.y, wreg[j].y);
            }
            float sdot = sum2(acc0) + sum2(acc1);
            partial[tid] = (tid < 128) ? (sdot + xcur) : sdot;
            __syncthreads();

            if (tid < 32) {
                float iv = partial[tid]      + partial[tid + 128];
                float fv = partial[tid + 32] + partial[tid + 160];
                float gv = partial[tid + 64] + partial[tid + 192];
                float ov = partial[tid + 96] + partial[tid + 224];
                float ig = sigmoid_fast(iv);
                float fg = sigmoid_fast(fv);
                float og = sigmoid_fast(ov);
                float gg = tanh_fast(gv);
                creg = fmaf(fg, creg, ig * gg);
                float h = og * tanh_fast(creg);

                const long m = midx(qi);
                if (layer == 0) {
                    __nv_bfloat16 hb16 = __float2bfloat16_rn(h);
                    float hf = __bfloat162float(hb16);
                    __nv_bfloat16 lb16 = __float2bfloat16_rn(h - hf);
                    a2[m * KA + ycol]       = hb16;
                    a2[m * KA + 512 + ycol] = lb16;
                } else {
                    y1[m * Hn + ycol] = h;
                }

                const int pn = p ^ 1;
                unsigned ldst = smem_u32(&h_buf[pn][unit]);
                unsigned lbar = pn ? mb1 : mb0;
#pragma unroll
                for (unsigned r = 0; r < 8; r++)
                    st_async_f32(mapa_cluster(ldst, r), h, mapa_cluster(lbar, r));
            }
            xcur = xnext;
        }

        // layer-0: publish a2 sample (g,s): 16 CTAs arrive (8 per dir-cluster)
        if (layer == 0) {
            if (tid < 32) __threadfence();
            __syncthreads();
            if (tid == 0) atomicAdd(&g_f0[s * 4 + group], 1u);
        }
    }

    mbar_wait(mb0, ph0);   // absorb final broadcast (4096 even -> mb0/ph0)
    cluster_sync_();
}

// ---------------------------------------------------------------------------
// 5) max over batch axis
// ---------------------------------------------------------------------------
__global__ void maxpool_kernel(const float* __restrict__ y1, float* __restrict__ out2)
{
    int idx = blockIdx.x * 256 + threadIdx.x;
    int s = idx >> 9, h = idx & 511;
    float mx = -3.402823466e38f;
    for (int b = 0; b < 128; b++) {
        float v = y1[((long)b * 128 + s) * Hn + h];
        mx = fmaxf(mx, v);
    }
    out2[idx] = mx;
}

// ---------------------------------------------------------------------------
extern "C" void kernel_launch(void* const* d_in, const int* in_sizes, int n_in,
                              void* d_out, int out_size)
{
    const int*   rt  = (const int*)d_in[0];
    const int*   re  = (const int*)d_in[1];
    const int*   rm  = (const int*)d_in[2];
    const float* h0  = (const float*)d_in[3];
    const float* c0  = (const float*)d_in[4];
    const float* Ert = (const float*)d_in[5];
    const float* Ere = (const float*)d_in[6];
    const float* Erm = (const float*)d_in[7];
    const float* Wih = (const float*)d_in[8];
    const float* Whh = (const float*)d_in[9];
    const float* bih = (const float*)d_in[10];
    const float* bhh = (const float*)d_in[11];

    float* out  = (float*)d_out;
    float* y1   = out;
    float* out2 = out + (long)Bn * Sn * Hn;

    void *p_x0, *p_x1, *p_a2, *p_w2;
    cudaGetSymbolAddress(&p_x0, g_x0);
    cudaGetSymbolAddress(&p_x1, g_x1);
    cudaGetSymbolAddress(&p_a2, g_a2);
    cudaGetSymbolAddress(&p_w2, g_w2);
    float* gx0 = (float*)p_x0;
    float* gx1 = (float*)p_x1;
    __nv_bfloat16* a2 = (__nv_bfloat16*)p_a2;
    __nv_bfloat16* w2 = (__nv_bfloat16*)p_w2;

    // lazily created side stream (non-blocking: no implicit legacy-stream deps)
    static cudaStream_t s2 = nullptr;
    static cudaEvent_t ev_fork = nullptr, ev_join = nullptr;
    if (!s2) {
        cudaStreamCreateWithFlags(&s2, cudaStreamNonBlocking);
        cudaEventCreateWithFlags(&ev_fork, cudaEventDisableTiming);
        cudaEventCreateWithFlags(&ev_join, cudaEventDisableTiming);
    }

    cudaFuncSetAttribute(gemm_mma_kernel,
                         cudaFuncAttributeMaxDynamicSharedMemorySize, GEMM_SMEM);
    cudaFuncSetAttribute(gemm_pipe_kernel,
                         cudaFuncAttributeMaxDynamicSharedMemorySize, GEMM_SMEM);

    // prep (default stream)
    zero_flags_kernel<<<1, 128>>>();
    embed_split_kernel<<<NROW, 128>>>(rt, re, rm, Ert, Ere, Erm);
    w_split_kernel<<<dim3(2048, 2), 128>>>(Wih);
    gemm_mma_kernel<<<dim3(16, 128), 256, GEMM_SMEM>>>(a2, w2, bih, bhh, gx0);

    // fork: persistent gemm on s2, persistent lstm on default stream
    const __nv_bfloat16* w2l1 = w2 + (long)2048 * KW;
    cudaEventRecord(ev_fork, 0);
    cudaStreamWaitEvent(s2, ev_fork, 0);
    gemm_pipe_kernel<<<NG, 256, GEMM_SMEM, s2>>>(a2, w2l1, bih + 2048, bhh + 2048, gx1);
    lstm_fused_kernel<<<128, 256>>>(Whh, gx0, gx1, y1, a2, h0, c0);
    cudaEventRecord(ev_join, s2);
    cudaStreamWaitEvent(0, ev_join, 0);

    maxpool_kernel<<<256, 256>>>(y1, out2);
}